// round 16
// baseline (speedup 1.0000x reference)
#include <cuda_runtime.h>
#include <cstdint>

// ---------------- problem constants ----------------
#define Bn   4
#define Nn   6
#define Hn   128
#define Wn   128
#define HWn  16384          // H*W
#define Ln   98304          // N*H*W
#define DIN  8              // D_INNER
#define DST  16             // D_STATE
#define Cn   128            // scan chunk length
#define NCH  768            // Ln / Cn

// ---------------- scratch (device globals; no runtime alloc) ----------------
static __device__ __align__(16) float g_xmpre[(size_t)Bn * Ln * DIN];
static __device__ __align__(16) float g_z    [(size_t)Bn * Ln * DIN];
static __device__ __align__(16) float g_out4 [(size_t)Bn * Ln * 4];
static __device__ float g_aggA[(size_t)Bn * NCH * 128];
static __device__ float g_aggB[(size_t)Bn * NCH * 128];
static __device__ float g_hpre[(size_t)Bn * NCH * 128];
static __device__ int   g_sp[HWn];
static __device__ int   g_base[8193];

// ---------------- helpers ----------------
__device__ __forceinline__ int d2_of(int j) {
    int y = j >> 7, x = j & 127;
    int dy = y - 64, dx = x - 64;
    return dy * dy + dx * dx;
}

__device__ __forceinline__ float silu_f(float x) {
    return x / (1.0f + __expf(-x));
}

__device__ __forceinline__ float softplus_f(float x) {
    return (x > 15.0f) ? x : log1pf(__expf(x));
}

// perms[k][l] computed inline from sp.
// k=0: scanA, k=1: scanB, k=2: scanA reversed, k=3: scanB reversed
__device__ __forceinline__ int permidx(int k, int l) {
    if (k & 2) l = Ln - 1 - l;
    if ((k & 1) == 0) {
        int n = l >> 14;              // HW = 2^14
        int j = l & (HWn - 1);
        return (n << 14) + g_sp[j];
    } else {
        int j = l / Nn;
        int n = l - j * Nn;
        int t = (j & 1) ? (Nn - 1 - n) : n;
        return (t << 14) + g_sp[j];
    }
}

// ---------------- K0a: histogram + exclusive scan of d2 bins ----------------
__global__ __launch_bounds__(1024) void k_build_base() {
    __shared__ int hist[8193];
    __shared__ int wsum[32];
    int tid = threadIdx.x;
    for (int i = tid; i < 8193; i += 1024) hist[i] = 0;
    __syncthreads();
    for (int j = tid; j < HWn; j += 1024) atomicAdd(&hist[d2_of(j)], 1);
    __syncthreads();

    int base = tid * 8;
    int loc[8];
    int s = 0;
#pragma unroll
    for (int t = 0; t < 8; t++) { loc[t] = s; s += hist[base + t]; }

    int lane = tid & 31, wid = tid >> 5;
    int v = s;
#pragma unroll
    for (int off = 1; off < 32; off <<= 1) {
        int n = __shfl_up_sync(0xffffffffu, v, off);
        if (lane >= off) v += n;
    }
    if (lane == 31) wsum[wid] = v;
    __syncthreads();
    if (wid == 0) {
        int w = wsum[lane];
        int wi = w;
#pragma unroll
        for (int off = 1; off < 32; off <<= 1) {
            int n = __shfl_up_sync(0xffffffffu, wi, off);
            if (lane >= off) wi += n;
        }
        wsum[lane] = wi - w;   // exclusive
    }
    __syncthreads();
    int excl = (v - s) + wsum[wid];
#pragma unroll
    for (int t = 0; t < 8; t++) g_base[base + t] = excl + loc[t];
    if (tid == 0) g_base[8192] = HWn - hist[8192];
}

// ---------------- K0b: stable rank + scatter -> sp ----------------
__global__ __launch_bounds__(256) void k_rank() {
    int j = blockIdx.x * 256 + threadIdx.x;
    int d2j = d2_of(j);
    int cnt = 0;
    for (int yp = 0; yp < 128; yp++) {
        int dy = yp - 64;
        int rem = d2j - dy * dy;
        if (rem < 0) continue;
        int k = __float2int_rd(sqrtf((float)rem));
        while ((k + 1) * (k + 1) <= rem) k++;
        while (k > 0 && k * k > rem) k--;
        if (k * k != rem) continue;
        int jb = yp << 7;
        int xa = 64 - k, xb = 64 + k;
        if (xa >= 0) { int jp = jb + xa; if (jp < j) cnt++; }
        if (k != 0 && xb < 128) { int jp = jb + xb; if (jp < j) cnt++; }
    }
    g_sp[g_base[d2j] + cnt] = j;
}

// ---------------- K1: gather + dwconv3 + silu + in_proj ----------------
__global__ __launch_bounds__(256) void k_front(const float* __restrict__ xin,
                                               const float* __restrict__ dww,
                                               const float* __restrict__ dwb,
                                               const float* __restrict__ ipw) {
    __shared__ float sw[80];   // [0..11] dwconv_w, [12..15] dwconv_b, [16..79] in_proj_w
    int tid = threadIdx.x;
    if (tid < 12) sw[tid] = dww[tid];
    if (tid < 4)  sw[12 + tid] = dwb[tid];
    if (tid < 64) sw[16 + tid] = ipw[tid];
    __syncthreads();

    int gid = blockIdx.x * 256 + tid;
    int b = gid / Ln;
    int l = gid - b * Ln;

    float u[4];
#pragma unroll
    for (int k = 0; k < 4; k++) {
        float acc = sw[12 + k];
#pragma unroll
        for (int t = 0; t < 3; t++) {
            int ll = l - 1 + t;
            float v = 0.0f;
            if (ll >= 0 && ll < Ln) {
                int p = permidx(k, ll);
                v = __ldg(&xin[(size_t)b * Ln + p]);
            }
            acc = fmaf(sw[k * 3 + t], v, acc);
        }
        u[k] = silu_f(acc);
    }

    float xm8[8], zz[8];
#pragma unroll
    for (int e = 0; e < 16; e++) {
        float a = 0.0f;
#pragma unroll
        for (int k = 0; k < 4; k++) a = fmaf(u[k], sw[16 + e * 4 + k], a);
        if (e < 8) xm8[e] = a; else zz[e - 8] = a;
    }

    float4* xp = (float4*)&g_xmpre[(size_t)gid * 8];
    xp[0] = make_float4(xm8[0], xm8[1], xm8[2], xm8[3]);
    xp[1] = make_float4(xm8[4], xm8[5], xm8[6], xm8[7]);
    float4* zp = (float4*)&g_z[(size_t)gid * 8];
    zp[0] = make_float4(zz[0], zz[1], zz[2], zz[3]);
    zp[1] = make_float4(zz[4], zz[5], zz[6], zz[7]);
}

// ---------------- shared phase A: conv4+silu -> xm; x_proj; softplus -> dt ----------------
// sw layout: [0..263] x_proj_w (33x8), [264..295] conv1d_w (8x4), [296..303] conv1d_b,
//            [304..311] dt_proj_w, [312..319] dt_proj_b
__device__ __forceinline__ void phaseA(int b, int l, int p, const float* sw,
                                       float (*s_dt)[8], float (*s_xm)[8],
                                       float (*s_Bm)[16], float (*s_Cm)[16], bool wantC) {
    float xc[8];
#pragma unroll
    for (int d = 0; d < 8; d++) xc[d] = sw[296 + d];
#pragma unroll
    for (int t = 0; t < 4; t++) {
        int lt = l - 3 + t;
        if (lt >= 0) {
            const float4* rp = (const float4*)&g_xmpre[((size_t)b * Ln + lt) * 8];
            float4 a0 = rp[0], a1 = rp[1];
            float vv[8] = {a0.x, a0.y, a0.z, a0.w, a1.x, a1.y, a1.z, a1.w};
#pragma unroll
            for (int d = 0; d < 8; d++) xc[d] = fmaf(sw[264 + d * 4 + t], vv[d], xc[d]);
        }
    }
    float xm[8];
    float dtraw = 0.0f;
#pragma unroll
    for (int d = 0; d < 8; d++) {
        xm[d] = silu_f(xc[d]);
        s_xm[p][d] = xm[d];
        dtraw = fmaf(xm[d], sw[d], dtraw);   // x_proj row 0
    }
#pragma unroll
    for (int s = 0; s < 16; s++) {
        float bm = 0.0f;
#pragma unroll
        for (int d = 0; d < 8; d++) bm = fmaf(xm[d], sw[(1 + s) * 8 + d], bm);
        s_Bm[p][s] = bm;
    }
    if (wantC) {
#pragma unroll
        for (int s = 0; s < 16; s++) {
            float cm = 0.0f;
#pragma unroll
            for (int d = 0; d < 8; d++) cm = fmaf(xm[d], sw[(17 + s) * 8 + d], cm);
            s_Cm[p][s] = cm;
        }
    }
#pragma unroll
    for (int d = 0; d < 8; d++) {
        s_dt[p][d] = softplus_f(fmaf(dtraw, sw[304 + d], sw[312 + d]));
    }
}

__device__ __forceinline__ void load_scan_weights(const float* __restrict__ xpw,
                                                  const float* __restrict__ c1w,
                                                  const float* __restrict__ c1b,
                                                  const float* __restrict__ dtpw,
                                                  const float* __restrict__ dtpb,
                                                  float* sw, int tid) {
    for (int i = tid; i < 264; i += 128) sw[i] = xpw[i];
    if (tid < 32) sw[264 + tid] = c1w[tid];
    if (tid < 8) {
        sw[296 + tid] = c1b[tid];
        sw[304 + tid] = dtpw[tid];
        sw[312 + tid] = dtpb[tid];
    }
}

// ---------------- K2a: chunk aggregates ----------------
__global__ __launch_bounds__(128) void k_scan_reduce(const float* __restrict__ xpw,
                                                     const float* __restrict__ c1w,
                                                     const float* __restrict__ c1b,
                                                     const float* __restrict__ dtpw,
                                                     const float* __restrict__ dtpb,
                                                     const float* __restrict__ alog) {
    __shared__ float sw[320];
    __shared__ float s_dt[Cn][8], s_xm[Cn][8], s_Bm[Cn][16];
    int tid = threadIdx.x;
    load_scan_weights(xpw, c1w, c1b, dtpw, dtpb, sw, tid);
    __syncthreads();

    int blk = blockIdx.x;
    int b = blk / NCH;
    int c = blk - b * NCH;
    int l0 = c * Cn;

    phaseA(b, l0 + tid, tid, sw, s_dt, s_xm, s_Bm, (float(*)[16])nullptr, false);
    __syncthreads();

    int d = tid >> 4, s = tid & 15;
    float Av = -__expf(__ldg(&alog[tid]));
    float ap = 1.0f, acc = 0.0f;
#pragma unroll 4
    for (int p = 0; p < Cn; p++) {
        float dtv = s_dt[p][d];
        float a = __expf(dtv * Av);
        float dbx = dtv * s_xm[p][d] * s_Bm[p][s];
        ap *= a;
        acc = fmaf(a, acc, dbx);
    }
    size_t idx = ((size_t)b * NCH + c) * 128 + tid;
    g_aggA[idx] = ap;
    g_aggB[idx] = acc;
}

// ---------------- K2b: sequential combine over chunks ----------------
__global__ __launch_bounds__(512) void k_scan_stage() {
    int tid = threadIdx.x;           // 512 = Bn * 128
    int b = tid >> 7, ch = tid & 127;
    float h = 0.0f;
    for (int c = 0; c < NCH; c++) {
        size_t idx = ((size_t)b * NCH + c) * 128 + ch;
        g_hpre[idx] = h;
        h = fmaf(g_aggA[idx], h, g_aggB[idx]);
    }
}

// ---------------- K2c: exact scan + fused epilogue ----------------
__global__ __launch_bounds__(128) void k_scan_apply(const float* __restrict__ xpw,
                                                    const float* __restrict__ c1w,
                                                    const float* __restrict__ c1b,
                                                    const float* __restrict__ dtpw,
                                                    const float* __restrict__ dtpb,
                                                    const float* __restrict__ alog,
                                                    const float* __restrict__ Dp,
                                                    const float* __restrict__ opw,
                                                    const float* __restrict__ lng,
                                                    const float* __restrict__ lnb) {
    __shared__ float sw[368];
    __shared__ float s_dt[Cn][8], s_xm[Cn][8], s_Bm[Cn][16], s_Cm[Cn][16], s_y[Cn][8];
    int tid = threadIdx.x;
    load_scan_weights(xpw, c1w, c1b, dtpw, dtpb, sw, tid);
    if (tid < 32) sw[320 + tid] = opw[tid];
    if (tid < 8)  sw[352 + tid] = Dp[tid];
    if (tid < 4) { sw[360 + tid] = lng[tid]; sw[364 + tid] = lnb[tid]; }
    __syncthreads();

    int blk = blockIdx.x;
    int b = blk / NCH;
    int c = blk - b * NCH;
    int l0 = c * Cn;

    phaseA(b, l0 + tid, tid, sw, s_dt, s_xm, s_Bm, s_Cm, true);
    __syncthreads();

    // phase B: thread per (d,s)
    {
        int d = tid >> 4, s = tid & 15;
        float Av = -__expf(__ldg(&alog[tid]));
        float h = g_hpre[((size_t)b * NCH + c) * 128 + tid];
#pragma unroll 4
        for (int p = 0; p < Cn; p++) {
            float dtv = s_dt[p][d];
            float a = __expf(dtv * Av);
            float dbx = dtv * s_xm[p][d] * s_Bm[p][s];
            h = fmaf(a, h, dbx);
            float yy = h * s_Cm[p][s];
            yy += __shfl_xor_sync(0xffffffffu, yy, 8);
            yy += __shfl_xor_sync(0xffffffffu, yy, 4);
            yy += __shfl_xor_sync(0xffffffffu, yy, 2);
            yy += __shfl_xor_sync(0xffffffffu, yy, 1);
            if (s == 0) s_y[p][d] = yy;
        }
    }
    __syncthreads();

    // phase C: one position per thread
    {
        int l = l0 + tid;
        const float4* zp = (const float4*)&g_z[((size_t)b * Ln + l) * 8];
        float4 z0 = zp[0], z1 = zp[1];
        float zz[8] = {z0.x, z0.y, z0.z, z0.w, z1.x, z1.y, z1.z, z1.w};
        float yv[8];
#pragma unroll
        for (int d = 0; d < 8; d++) {
            float y = s_y[tid][d] + s_xm[tid][d] * sw[352 + d];
            yv[d] = y * silu_f(zz[d]);
        }
        float o[4];
#pragma unroll
        for (int e = 0; e < 4; e++) {
            float a = 0.0f;
#pragma unroll
            for (int d = 0; d < 8; d++) a = fmaf(yv[d], sw[320 + e * 8 + d], a);
            o[e] = a;
        }
        float mu = 0.25f * (o[0] + o[1] + o[2] + o[3]);
        float var = 0.0f;
#pragma unroll
        for (int e = 0; e < 4; e++) { float dd = o[e] - mu; var = fmaf(dd, dd, var); }
        var *= 0.25f;
        float rs = rsqrtf(var + 1e-5f);
        float4 ov;
        ov.x = (o[0] - mu) * rs * sw[360] + sw[364];
        ov.y = (o[1] - mu) * rs * sw[361] + sw[365];
        ov.z = (o[2] - mu) * rs * sw[362] + sw[366];
        ov.w = (o[3] - mu) * rs * sw[363] + sw[367];
        *(float4*)&g_out4[((size_t)b * Ln + l) * 4] = ov;
    }
}

// ---------------- K3: final permuted gather + mean ----------------
__global__ __launch_bounds__(256) void k_finish(float* __restrict__ dout) {
    int gid = blockIdx.x * 256 + threadIdx.x;
    int b = gid / Ln;
    int i = gid - b * Ln;
    float acc = 0.0f;
#pragma unroll
    for (int k = 0; k < 4; k++) {
        int p = permidx(k, i);
        acc += __ldg(&g_out4[((size_t)b * Ln + p) * 4 + k]);
    }
    dout[gid] = 0.25f * acc;
}

// ---------------- launch ----------------
extern "C" void kernel_launch(void* const* d_in, const int* in_sizes, int n_in,
                              void* d_out, int out_size) {
    const float* x    = (const float*)d_in[0];
    const float* dww  = (const float*)d_in[1];
    const float* dwb  = (const float*)d_in[2];
    const float* ipw  = (const float*)d_in[3];
    const float* c1w  = (const float*)d_in[4];
    const float* c1b  = (const float*)d_in[5];
    const float* xpw  = (const float*)d_in[6];
    const float* dtpw = (const float*)d_in[7];
    const float* dtpb = (const float*)d_in[8];
    const float* alog = (const float*)d_in[9];
    const float* Dp   = (const float*)d_in[10];
    const float* opw  = (const float*)d_in[11];
    const float* lng  = (const float*)d_in[12];
    const float* lnb  = (const float*)d_in[13];
    float* out = (float*)d_out;

    k_build_base<<<1, 1024>>>();
    k_rank<<<HWn / 256, 256>>>();
    k_front<<<(Bn * Ln) / 256, 256>>>(x, dww, dwb, ipw);
    k_scan_reduce<<<Bn * NCH, 128>>>(xpw, c1w, c1b, dtpw, dtpb, alog);
    k_scan_stage<<<1, 512>>>();
    k_scan_apply<<<Bn * NCH, 128>>>(xpw, c1w, c1b, dtpw, dtpb, alog, Dp, opw, lng, lnb);
    k_finish<<<(Bn * Ln) / 256, 256>>>(out);
}

// round 17
// speedup vs baseline: 2.0739x; 2.0739x over previous
#include <cuda_runtime.h>
#include <cstdint>

// ---------------- problem constants ----------------
#define Bn   4
#define Nn   6
#define Hn   128
#define Wn   128
#define HWn  16384          // H*W
#define Ln   98304          // N*H*W
#define DIN  8              // D_INNER
#define DST  16             // D_STATE
#define Cn   128            // scan chunk length
#define NCH  768            // Ln / Cn
#define SCH  32             // chunks per superchunk
#define NSC  24             // NCH / SCH

// ---------------- scratch (device globals; no runtime alloc) ----------------
static __device__ __align__(16) float g_xmpre[(size_t)Bn * Ln * DIN];
static __device__ __align__(16) float g_z    [(size_t)Bn * Ln * DIN];
static __device__ __align__(16) float g_out4 [(size_t)Bn * Ln * 4];
static __device__ float g_aggA[(size_t)Bn * NCH * 128];
static __device__ float g_aggB[(size_t)Bn * NCH * 128];
static __device__ float g_hpre[(size_t)Bn * NCH * 128];
static __device__ float g_supA[(size_t)Bn * NSC * 128];
static __device__ float g_supB[(size_t)Bn * NSC * 128];
static __device__ float g_hsup[(size_t)Bn * NSC * 128];
static __device__ int   g_sp[HWn];
static __device__ int   g_base[8193];

// ---------------- helpers ----------------
__device__ __forceinline__ int d2_of(int j) {
    int y = j >> 7, x = j & 127;
    int dy = y - 64, dx = x - 64;
    return dy * dy + dx * dx;
}

__device__ __forceinline__ float silu_f(float x) {
    return x / (1.0f + __expf(-x));
}

__device__ __forceinline__ float softplus_f(float x) {
    return (x > 15.0f) ? x : log1pf(__expf(x));
}

// perms[k][l] computed inline from sp.
__device__ __forceinline__ int permidx(int k, int l) {
    if (k & 2) l = Ln - 1 - l;
    if ((k & 1) == 0) {
        int n = l >> 14;              // HW = 2^14
        int j = l & (HWn - 1);
        return (n << 14) + g_sp[j];
    } else {
        int j = l / Nn;
        int n = l - j * Nn;
        int t = (j & 1) ? (Nn - 1 - n) : n;
        return (t << 14) + g_sp[j];
    }
}

// ---------------- K0a: histogram + exclusive scan of d2 bins ----------------
__global__ __launch_bounds__(1024) void k_build_base() {
    __shared__ int hist[8193];
    __shared__ int wsum[32];
    int tid = threadIdx.x;
    for (int i = tid; i < 8193; i += 1024) hist[i] = 0;
    __syncthreads();
    for (int j = tid; j < HWn; j += 1024) atomicAdd(&hist[d2_of(j)], 1);
    __syncthreads();

    int base = tid * 8;
    int loc[8];
    int s = 0;
#pragma unroll
    for (int t = 0; t < 8; t++) { loc[t] = s; s += hist[base + t]; }

    int lane = tid & 31, wid = tid >> 5;
    int v = s;
#pragma unroll
    for (int off = 1; off < 32; off <<= 1) {
        int n = __shfl_up_sync(0xffffffffu, v, off);
        if (lane >= off) v += n;
    }
    if (lane == 31) wsum[wid] = v;
    __syncthreads();
    if (wid == 0) {
        int w = wsum[lane];
        int wi = w;
#pragma unroll
        for (int off = 1; off < 32; off <<= 1) {
            int n = __shfl_up_sync(0xffffffffu, wi, off);
            if (lane >= off) wi += n;
        }
        wsum[lane] = wi - w;   // exclusive
    }
    __syncthreads();
    int excl = (v - s) + wsum[wid];
#pragma unroll
    for (int t = 0; t < 8; t++) g_base[base + t] = excl + loc[t];
    if (tid == 0) g_base[8192] = HWn - hist[8192];
}

// ---------------- K0b: stable rank + scatter -> sp ----------------
__global__ __launch_bounds__(256) void k_rank() {
    int j = blockIdx.x * 256 + threadIdx.x;
    int d2j = d2_of(j);
    int cnt = 0;
    for (int yp = 0; yp < 128; yp++) {
        int dy = yp - 64;
        int rem = d2j - dy * dy;
        if (rem < 0) continue;
        int k = __float2int_rd(sqrtf((float)rem));
        while ((k + 1) * (k + 1) <= rem) k++;
        while (k > 0 && k * k > rem) k--;
        if (k * k != rem) continue;
        int jb = yp << 7;
        int xa = 64 - k, xb = 64 + k;
        if (xa >= 0) { int jp = jb + xa; if (jp < j) cnt++; }
        if (k != 0 && xb < 128) { int jp = jb + xb; if (jp < j) cnt++; }
    }
    g_sp[g_base[d2j] + cnt] = j;
}

// ---------------- K1: gather + dwconv3 + silu + in_proj ----------------
__global__ __launch_bounds__(256) void k_front(const float* __restrict__ xin,
                                               const float* __restrict__ dww,
                                               const float* __restrict__ dwb,
                                               const float* __restrict__ ipw) {
    __shared__ float sw[80];   // [0..11] dwconv_w, [12..15] dwconv_b, [16..79] in_proj_w
    int tid = threadIdx.x;
    if (tid < 12) sw[tid] = dww[tid];
    if (tid < 4)  sw[12 + tid] = dwb[tid];
    if (tid < 64) sw[16 + tid] = ipw[tid];
    __syncthreads();

    int gid = blockIdx.x * 256 + tid;
    int b = gid / Ln;
    int l = gid - b * Ln;
    int lane = tid & 31;
    const float* xb = xin + (size_t)b * Ln;

    float u[4];
#pragma unroll
    for (int k = 0; k < 4; k++) {
        int p = permidx(k, l);
        float v = __ldg(&xb[p]);
        float vm = __shfl_up_sync(0xffffffffu, v, 1);
        float vp = __shfl_down_sync(0xffffffffu, v, 1);
        if (lane == 0)  vm = (l - 1 >= 0) ? __ldg(&xb[permidx(k, l - 1)]) : 0.0f;
        if (lane == 31) vp = (l + 1 < Ln) ? __ldg(&xb[permidx(k, l + 1)]) : 0.0f;
        float acc = sw[12 + k];
        acc = fmaf(sw[k * 3 + 0], vm, acc);
        acc = fmaf(sw[k * 3 + 1], v,  acc);
        acc = fmaf(sw[k * 3 + 2], vp, acc);
        u[k] = silu_f(acc);
    }

    float xm8[8], zz[8];
#pragma unroll
    for (int e = 0; e < 16; e++) {
        float a = 0.0f;
#pragma unroll
        for (int k = 0; k < 4; k++) a = fmaf(u[k], sw[16 + e * 4 + k], a);
        if (e < 8) xm8[e] = a; else zz[e - 8] = a;
    }

    float4* xp = (float4*)&g_xmpre[(size_t)gid * 8];
    xp[0] = make_float4(xm8[0], xm8[1], xm8[2], xm8[3]);
    xp[1] = make_float4(xm8[4], xm8[5], xm8[6], xm8[7]);
    float4* zp = (float4*)&g_z[(size_t)gid * 8];
    zp[0] = make_float4(zz[0], zz[1], zz[2], zz[3]);
    zp[1] = make_float4(zz[4], zz[5], zz[6], zz[7]);
}

// ---------------- shared phase A (transposed smem, conflict-free) ----------------
// sw layout: [0..263] x_proj_w (33x8), [264..295] conv1d_w (8x4), [296..303] conv1d_b,
//            [304..311] dt_proj_w, [312..319] dt_proj_b
// s_dt/s_dtxm/s_xm: [d][128]; s_Bm/s_Cm: [s][129] (padded).
template<bool WANT_XM, bool WANT_C>
__device__ __forceinline__ void phaseA(int b, int l, int p, const float* sw,
                                       float* s_dt, float* s_dtxm, float* s_xm,
                                       float* s_Bm, float* s_Cm) {
    float xc[8];
#pragma unroll
    for (int d = 0; d < 8; d++) xc[d] = sw[296 + d];
#pragma unroll
    for (int t = 0; t < 4; t++) {
        int lt = l - 3 + t;
        if (lt >= 0) {
            const float4* rp = (const float4*)&g_xmpre[((size_t)b * Ln + lt) * 8];
            float4 a0 = rp[0], a1 = rp[1];
            float vv[8] = {a0.x, a0.y, a0.z, a0.w, a1.x, a1.y, a1.z, a1.w};
#pragma unroll
            for (int d = 0; d < 8; d++) xc[d] = fmaf(sw[264 + d * 4 + t], vv[d], xc[d]);
        }
    }
    float xm[8];
    float dtraw = 0.0f;
#pragma unroll
    for (int d = 0; d < 8; d++) {
        xm[d] = silu_f(xc[d]);
        dtraw = fmaf(xm[d], sw[d], dtraw);   // x_proj row 0
    }
#pragma unroll
    for (int d = 0; d < 8; d++) {
        float dt = softplus_f(fmaf(dtraw, sw[304 + d], sw[312 + d]));
        s_dt[d * 128 + p] = dt;
        s_dtxm[d * 128 + p] = dt * xm[d];
        if (WANT_XM) s_xm[d * 128 + p] = xm[d];
    }
#pragma unroll
    for (int s = 0; s < 16; s++) {
        float bm = 0.0f;
#pragma unroll
        for (int d = 0; d < 8; d++) bm = fmaf(xm[d], sw[(1 + s) * 8 + d], bm);
        s_Bm[s * 129 + p] = bm;
    }
    if (WANT_C) {
#pragma unroll
        for (int s = 0; s < 16; s++) {
            float cm = 0.0f;
#pragma unroll
            for (int d = 0; d < 8; d++) cm = fmaf(xm[d], sw[(17 + s) * 8 + d], cm);
            s_Cm[s * 129 + p] = cm;
        }
    }
}

__device__ __forceinline__ void load_scan_weights(const float* __restrict__ xpw,
                                                  const float* __restrict__ c1w,
                                                  const float* __restrict__ c1b,
                                                  const float* __restrict__ dtpw,
                                                  const float* __restrict__ dtpb,
                                                  float* sw, int tid) {
    for (int i = tid; i < 264; i += 128) sw[i] = xpw[i];
    if (tid < 32) sw[264 + tid] = c1w[tid];
    if (tid < 8) {
        sw[296 + tid] = c1b[tid];
        sw[304 + tid] = dtpw[tid];
        sw[312 + tid] = dtpb[tid];
    }
}

// ---------------- K2a: chunk aggregates ----------------
__global__ __launch_bounds__(128) void k_scan_reduce(const float* __restrict__ xpw,
                                                     const float* __restrict__ c1w,
                                                     const float* __restrict__ c1b,
                                                     const float* __restrict__ dtpw,
                                                     const float* __restrict__ dtpb,
                                                     const float* __restrict__ alog) {
    __shared__ float sw[320];
    __shared__ float s_dt[8 * 128], s_dtxm[8 * 128], s_Bm[16 * 129];
    int tid = threadIdx.x;
    load_scan_weights(xpw, c1w, c1b, dtpw, dtpb, sw, tid);
    __syncthreads();

    int blk = blockIdx.x;
    int b = blk / NCH;
    int c = blk - b * NCH;
    int l0 = c * Cn;

    phaseA<false, false>(b, l0 + tid, tid, sw, s_dt, s_dtxm, nullptr, s_Bm, nullptr);
    __syncthreads();

    float Av = -__expf(__ldg(&alog[tid]));
    const float* pdt   = s_dt   + (tid >> 4) * 128;
    const float* pdtxm = s_dtxm + (tid >> 4) * 128;
    const float* pBm   = s_Bm   + (tid & 15) * 129;
    float ap = 1.0f, acc = 0.0f;
#pragma unroll 8
    for (int p = 0; p < Cn; p++) {
        float dtv = pdt[p];
        float a = __expf(dtv * Av);
        float dbx = pdtxm[p] * pBm[p];
        ap *= a;
        acc = fmaf(a, acc, dbx);
    }
    size_t idx = ((size_t)b * NCH + c) * 128 + tid;
    g_aggA[idx] = ap;
    g_aggB[idx] = acc;
}

// ---------------- K2b-1: superchunk aggregates (parallel, coalesced) ----------------
__global__ __launch_bounds__(128) void k_stage1() {
    int blk = blockIdx.x;           // Bn * NSC
    int b = blk / NSC;
    int sc = blk - b * NSC;
    int tid = threadIdx.x;
    float ap = 1.0f, acc = 0.0f;
    size_t idx = ((size_t)b * NCH + sc * SCH) * 128 + tid;
#pragma unroll 8
    for (int i = 0; i < SCH; i++) {
        float a = g_aggA[idx];
        float bb = g_aggB[idx];
        acc = fmaf(a, acc, bb);
        ap *= a;
        idx += 128;
    }
    size_t o = ((size_t)b * NSC + sc) * 128 + tid;
    g_supA[o] = ap;
    g_supB[o] = acc;
}

// ---------------- K2b-2: tiny serial combine over 24 superchunks ----------------
__global__ __launch_bounds__(512) void k_stage2() {
    int tid = threadIdx.x;           // 512 = Bn * 128
    int b = tid >> 7, ch = tid & 127;
    size_t base = (size_t)b * NSC * 128 + ch;
    float As[NSC], Bs[NSC];
#pragma unroll
    for (int sc = 0; sc < NSC; sc++) {
        As[sc] = g_supA[base + (size_t)sc * 128];
        Bs[sc] = g_supB[base + (size_t)sc * 128];
    }
    float h = 0.0f;
#pragma unroll
    for (int sc = 0; sc < NSC; sc++) {
        g_hsup[base + (size_t)sc * 128] = h;
        h = fmaf(As[sc], h, Bs[sc]);
    }
}

// ---------------- K2b-3: expand to per-chunk entry states (parallel) ----------------
__global__ __launch_bounds__(128) void k_stage3() {
    int blk = blockIdx.x;           // Bn * NSC
    int b = blk / NSC;
    int sc = blk - b * NSC;
    int tid = threadIdx.x;
    float h = g_hsup[((size_t)b * NSC + sc) * 128 + tid];
    size_t idx = ((size_t)b * NCH + sc * SCH) * 128 + tid;
#pragma unroll 8
    for (int i = 0; i < SCH; i++) {
        g_hpre[idx] = h;
        h = fmaf(g_aggA[idx], h, g_aggB[idx]);
        idx += 128;
    }
}

// ---------------- K2c: exact scan + fused epilogue ----------------
__global__ __launch_bounds__(128) void k_scan_apply(const float* __restrict__ xpw,
                                                    const float* __restrict__ c1w,
                                                    const float* __restrict__ c1b,
                                                    const float* __restrict__ dtpw,
                                                    const float* __restrict__ dtpb,
                                                    const float* __restrict__ alog,
                                                    const float* __restrict__ Dp,
                                                    const float* __restrict__ opw,
                                                    const float* __restrict__ lng,
                                                    const float* __restrict__ lnb) {
    __shared__ float sw[368];
    __shared__ float s_dt[8 * 128], s_dtxm[8 * 128], s_xm[8 * 128];
    __shared__ float s_Bm[16 * 129], s_Cm[16 * 129];
    __shared__ float s_y[8 * 128];
    int tid = threadIdx.x;
    load_scan_weights(xpw, c1w, c1b, dtpw, dtpb, sw, tid);
    if (tid < 32) sw[320 + tid] = opw[tid];
    if (tid < 8)  sw[352 + tid] = Dp[tid];
    if (tid < 4) { sw[360 + tid] = lng[tid]; sw[364 + tid] = lnb[tid]; }
    __syncthreads();

    int blk = blockIdx.x;
    int b = blk / NCH;
    int c = blk - b * NCH;
    int l0 = c * Cn;

    phaseA<true, true>(b, l0 + tid, tid, sw, s_dt, s_dtxm, s_xm, s_Bm, s_Cm);
    __syncthreads();

    // phase B: thread per (d,s)
    {
        int d = tid >> 4, s = tid & 15;
        float Av = -__expf(__ldg(&alog[tid]));
        float h = g_hpre[((size_t)b * NCH + c) * 128 + tid];
        const float* pdt   = s_dt   + d * 128;
        const float* pdtxm = s_dtxm + d * 128;
        const float* pBm   = s_Bm   + s * 129;
        const float* pCm   = s_Cm   + s * 129;
        float* py = s_y + d * 128;
#pragma unroll 4
        for (int p = 0; p < Cn; p++) {
            float dtv = pdt[p];
            float a = __expf(dtv * Av);
            float dbx = pdtxm[p] * pBm[p];
            h = fmaf(a, h, dbx);
            float yy = h * pCm[p];
            yy += __shfl_xor_sync(0xffffffffu, yy, 8);
            yy += __shfl_xor_sync(0xffffffffu, yy, 4);
            yy += __shfl_xor_sync(0xffffffffu, yy, 2);
            yy += __shfl_xor_sync(0xffffffffu, yy, 1);
            if (s == 0) py[p] = yy;
        }
    }
    __syncthreads();

    // phase C: one position per thread
    {
        int l = l0 + tid;
        const float4* zp = (const float4*)&g_z[((size_t)b * Ln + l) * 8];
        float4 z0 = zp[0], z1 = zp[1];
        float zz[8] = {z0.x, z0.y, z0.z, z0.w, z1.x, z1.y, z1.z, z1.w};
        float yv[8];
#pragma unroll
        for (int d = 0; d < 8; d++) {
            float y = s_y[d * 128 + tid] + s_xm[d * 128 + tid] * sw[352 + d];
            yv[d] = y * silu_f(zz[d]);
        }
        float o[4];
#pragma unroll
        for (int e = 0; e < 4; e++) {
            float a = 0.0f;
#pragma unroll
            for (int d = 0; d < 8; d++) a = fmaf(yv[d], sw[320 + e * 8 + d], a);
            o[e] = a;
        }
        float mu = 0.25f * (o[0] + o[1] + o[2] + o[3]);
        float var = 0.0f;
#pragma unroll
        for (int e = 0; e < 4; e++) { float dd = o[e] - mu; var = fmaf(dd, dd, var); }
        var *= 0.25f;
        float rs = rsqrtf(var + 1e-5f);
        float4 ov;
        ov.x = (o[0] - mu) * rs * sw[360] + sw[364];
        ov.y = (o[1] - mu) * rs * sw[361] + sw[365];
        ov.z = (o[2] - mu) * rs * sw[362] + sw[366];
        ov.w = (o[3] - mu) * rs * sw[363] + sw[367];
        *(float4*)&g_out4[((size_t)b * Ln + l) * 4] = ov;
    }
}

// ---------------- K3: final permuted gather + mean ----------------
__global__ __launch_bounds__(256) void k_finish(float* __restrict__ dout) {
    int gid = blockIdx.x * 256 + threadIdx.x;
    int b = gid / Ln;
    int i = gid - b * Ln;
    float acc = 0.0f;
#pragma unroll
    for (int k = 0; k < 4; k++) {
        int p = permidx(k, i);
        acc += __ldg(&g_out4[((size_t)b * Ln + p) * 4 + k]);
    }
    dout[gid] = 0.25f * acc;
}

// ---------------- launch ----------------
extern "C" void kernel_launch(void* const* d_in, const int* in_sizes, int n_in,
                              void* d_out, int out_size) {
    const float* x    = (const float*)d_in[0];
    const float* dww  = (const float*)d_in[1];
    const float* dwb  = (const float*)d_in[2];
    const float* ipw  = (const float*)d_in[3];
    const float* c1w  = (const float*)d_in[4];
    const float* c1b  = (const float*)d_in[5];
    const float* xpw  = (const float*)d_in[6];
    const float* dtpw = (const float*)d_in[7];
    const float* dtpb = (const float*)d_in[8];
    const float* alog = (const float*)d_in[9];
    const float* Dp   = (const float*)d_in[10];
    const float* opw  = (const float*)d_in[11];
    const float* lng  = (const float*)d_in[12];
    const float* lnb  = (const float*)d_in[13];
    float* out = (float*)d_out;

    k_build_base<<<1, 1024>>>();
    k_rank<<<HWn / 256, 256>>>();
    k_front<<<(Bn * Ln) / 256, 256>>>(x, dww, dwb, ipw);
    k_scan_reduce<<<Bn * NCH, 128>>>(xpw, c1w, c1b, dtpw, dtpb, alog);
    k_stage1<<<Bn * NSC, 128>>>();
    k_stage2<<<1, 512>>>();
    k_stage3<<<Bn * NSC, 128>>>();
    k_scan_apply<<<Bn * NCH, 128>>>(xpw, c1w, c1b, dtpw, dtpb, alog, Dp, opw, lng, lnb);
    k_finish<<<(Bn * Ln) / 256, 256>>>(out);
}